// round 16
// baseline (speedup 1.0000x reference)
#include <cuda_runtime.h>
#include <cstdint>

#define NSEQ 768
#define CDIM 128
#define NR (NSEQ*NSEQ)          /* 589824 */
#define LNEPS 1e-5f

static constexpr size_t BUF_ELEMS = (size_t)CDIM * NR;

/* K-pair permuted layouts: within each 8-group of the contraction dim,
   element k sits at offset (k&~7) + 2*(k&3) + ((k&4)>>2). */
__device__ float g_x[BUF_ELEMS];       /* LN'd, tf32, permuted [row][perm(c)] */
__device__ float g_wpg[512*CDIM];      /* interleaved proj/gate rows (512), tf32, permuted */
__device__ float g_wgl[CDIM*CDIM];     /* w_glin, tf32, permuted */
__device__ float g_wout[CDIM*CDIM];    /* w_out, tf32, permuted */
__device__ float g_a[BUF_ELEMS];       /* [c][i][perm(k)] tf32 */
__device__ float g_b[BUF_ELEMS];       /* [c][j][perm(k)] tf32 */
__device__ float g_glin[BUF_ELEMS];    /* [row][c] sigmoid, fp32, plain */
__device__ float g_tri[BUF_ELEMS];     /* [c][i][j] plain */

/* ---------------- helpers ------------------------------------------ */
__device__ __forceinline__ uint32_t smem_u32(const void* p) {
    uint32_t a;
    asm("{ .reg .u64 t; cvta.to.shared.u64 t, %1; cvt.u32.u64 %0, t; }"
        : "=r"(a) : "l"(p));
    return a;
}
__device__ __forceinline__ uint32_t tf32u(float x) {
    uint32_t r;
    asm("cvt.rna.tf32.f32 %0, %1;" : "=r"(r) : "f"(x));
    return r;
}
__device__ __forceinline__ float tf32f(float x) { return __uint_as_float(tf32u(x)); }
__device__ __forceinline__ float sigm(float x)  { return 1.f / (1.f + __expf(-x)); }
__device__ __forceinline__ int   perm8(int k)   { return (k & ~7) + 2*(k&3) + ((k&4)>>2); }

__device__ __forceinline__ void mma8(float* c, uint32_t a0, uint32_t a1,
                                     uint32_t a2, uint32_t a3,
                                     uint32_t b0, uint32_t b1) {
    asm volatile(
        "mma.sync.aligned.m16n8k8.row.col.f32.tf32.tf32.f32 "
        "{%0,%1,%2,%3}, {%4,%5,%6,%7}, {%8,%9}, {%0,%1,%2,%3};"
        : "+f"(c[0]), "+f"(c[1]), "+f"(c[2]), "+f"(c[3])
        : "r"(a0), "r"(a1), "r"(a2), "r"(a3), "r"(b0), "r"(b1));
}
__device__ __forceinline__ void cp16(uint32_t d, const void* s) {
    asm volatile("cp.async.cg.shared.global [%0], [%1], 16;" :: "r"(d), "l"(s));
}
__device__ __forceinline__ void cp_commit() { asm volatile("cp.async.commit_group;"); }
__device__ __forceinline__ void cp_wait1()  { asm volatile("cp.async.wait_group 1;"); }
__device__ __forceinline__ void cp_wait0()  { asm volatile("cp.async.wait_group 0;"); }

/* smem rows: 32 data floats padded to 40 (160B, 16B-aligned) */
#define SMPAD 40
#define ROWB  160
#define TILE128 20480          /* 128*160 */

/* ------------------------------------------------------------------ */
/* K0: LN + tf32 round + permute -> g_x. warp per row.                 */
/* ------------------------------------------------------------------ */
__global__ void k_ln(const float* __restrict__ pair,
                     const float* __restrict__ lnw, const float* __restrict__ lnb)
{
    int row  = blockIdx.x * 8 + (threadIdx.x >> 5);
    int lane = threadIdx.x & 31;
    float4 v = ((const float4*)(pair + (size_t)row * CDIM))[lane];
    float s  = v.x + v.y + v.z + v.w;
    float s2 = v.x*v.x + v.y*v.y + v.z*v.z + v.w*v.w;
#pragma unroll
    for (int o = 16; o > 0; o >>= 1) {
        s  += __shfl_xor_sync(0xffffffffu, s,  o);
        s2 += __shfl_xor_sync(0xffffffffu, s2, o);
    }
    float m  = s * (1.f/CDIM);
    float rs = rsqrtf(s2 * (1.f/CDIM) - m*m + LNEPS);
    int c0 = lane * 4;
    float* dst = g_x + (size_t)row * CDIM;
    float o0 = tf32f((v.x - m) * rs * __ldg(lnw+c0+0) + __ldg(lnb+c0+0));
    float o1 = tf32f((v.y - m) * rs * __ldg(lnw+c0+1) + __ldg(lnb+c0+1));
    float o2 = tf32f((v.z - m) * rs * __ldg(lnw+c0+2) + __ldg(lnb+c0+2));
    float o3 = tf32f((v.w - m) * rs * __ldg(lnw+c0+3) + __ldg(lnb+c0+3));
    dst[perm8(c0+0)] = o0; dst[perm8(c0+1)] = o1;
    dst[perm8(c0+2)] = o2; dst[perm8(c0+3)] = o3;
}

/* ------------------------------------------------------------------ */
/* K0b: round+permute weights. g_wpg row q (0..511):                   */
/*      q even -> proj[q>>1], q odd -> gate[q>>1]. Then wgl, wout.     */
/* ------------------------------------------------------------------ */
__global__ void k_round_w(const float* __restrict__ wp, const float* __restrict__ wg,
                          const float* __restrict__ wgl, const float* __restrict__ wout)
{
    int i4 = blockIdx.x * 256 + threadIdx.x;
    if (i4 < 16384) {
        int q = i4 >> 5, kq = (i4 & 31) * 4;
        const float* src = ((q & 1) ? wg : wp) + (size_t)(q >> 1) * CDIM + kq;
        float* dst = g_wpg + (size_t)q * CDIM;
        float4 v = *(const float4*)src;
        dst[perm8(kq+0)] = tf32f(v.x); dst[perm8(kq+1)] = tf32f(v.y);
        dst[perm8(kq+2)] = tf32f(v.z); dst[perm8(kq+3)] = tf32f(v.w);
    } else if (i4 < 20480) {
        int j = i4 - 16384, q = j >> 5, kq = (j & 31) * 4;
        float4 v = *(const float4*)(wgl + (size_t)q * CDIM + kq);
        float* dst = g_wgl + (size_t)q * CDIM;
        dst[perm8(kq+0)] = tf32f(v.x); dst[perm8(kq+1)] = tf32f(v.y);
        dst[perm8(kq+2)] = tf32f(v.z); dst[perm8(kq+3)] = tf32f(v.w);
    } else if (i4 < 24576) {
        int j = i4 - 20480, q = j >> 5, kq = (j & 31) * 4;
        float4 v = *(const float4*)(wout + (size_t)q * CDIM + kq);
        float* dst = g_wout + (size_t)q * CDIM;
        dst[perm8(kq+0)] = tf32f(v.x); dst[perm8(kq+1)] = tf32f(v.y);
        dst[perm8(kq+2)] = tf32f(v.z); dst[perm8(kq+3)] = tf32f(v.w);
    }
}

/* ------------------------------------------------------------------ */
/* K2 (merged pg+glin): block handles TWO 128-row tiles as one 8-chunk */
/* continuous pipeline. grid (5, NR/256): x<4 -> proj/gate jo block,   */
/* x==4 -> glin. warp 64x32, acc=64 regs, 2 CTAs/SM.                   */
/* ------------------------------------------------------------------ */
__device__ __forceinline__ void pg_epilogue(
    float (&acc)[4][4][4], int rowbase, int jbase, int is_gl,
    int mrow, int ncol, int g, int tig)
{
    if (!is_gl) {
        int pg_off = 2*(g & 3) + ((g & 4) >> 2);
#pragma unroll
        for (int mt = 0; mt < 4; mt++)
#pragma unroll
            for (int nt = 0; nt < 4; nt++) {
                int rg = rowbase + mrow + mt*16 + g;
                int n0 = ncol + nt*8 + tig*2;
                int jo = jbase + (n0 >> 1);
                float* dst = (jo & 1) ? g_b : g_a;
                size_t base = (size_t)(jo >> 1) * NR + (rg - g) + pg_off;
                dst[base]     = tf32f(acc[mt][nt][0] * sigm(acc[mt][nt][1]));
                dst[base + 8] = tf32f(acc[mt][nt][2] * sigm(acc[mt][nt][3]));
            }
    } else {
#pragma unroll
        for (int mt = 0; mt < 4; mt++)
#pragma unroll
            for (int nt = 0; nt < 4; nt++) {
                int rg = rowbase + mrow + mt*16 + g;
                int col = ncol + nt*8 + tig*2;
                *(float2*)(g_glin + (size_t)rg * CDIM + col) =
                    make_float2(sigm(acc[mt][nt][0]), sigm(acc[mt][nt][1]));
                *(float2*)(g_glin + (size_t)(rg+8) * CDIM + col) =
                    make_float2(sigm(acc[mt][nt][2]), sigm(acc[mt][nt][3]));
            }
    }
}

__global__ __launch_bounds__(256, 2) void k_pg_m()
{
    extern __shared__ float dsm[];
    float (*SA)[2][128][SMPAD] = (float(*)[2][128][SMPAD])dsm;
    float (*SB)[2][128][SMPAD] = (float(*)[2][128][SMPAD])(dsm + 2*128*SMPAD);
    uint32_t sb = smem_u32(dsm);
    uint32_t bA[2] = { sb, sb + TILE128 };
    uint32_t bB[2] = { sb + 2*TILE128, sb + 3*TILE128 };

    int t = threadIdx.x, warp = t >> 5, lane = t & 31;
    int g = lane >> 2, tig = lane & 3;
    int bx = blockIdx.x;
    int rowbase0 = blockIdx.y * 256;
    int is_gl = (bx == 4);
    int jbase  = bx * 64;
    int mrow = (warp >> 2) * 64, ncol = (warp & 3) * 32;

    const float* Bw = is_gl ? g_wgl : (g_wpg + (size_t)(jbase * 2) * CDIM);

    float acc[4][4][4] = {};

    /* global-chunk gc 0..7: row-tile = gc>>2, K-chunk = gc&3 */
#define PG_FILLG(GC, P)                                                        \
    {   const float* As_ = g_x + (size_t)(rowbase0 + ((GC) >> 2) * 128) * CDIM \
                           + ((GC) & 3) * 32;                                  \
        const float* Bs_ = Bw + ((GC) & 3) * 32;                               \
        _Pragma("unroll")                                                      \
        for (int q = 0; q < 4; q++) { int o = t + q*256, r = o >> 3, sg = o & 7; \
            cp16(bA[P] + r*ROWB + sg*16, As_ + (size_t)r*CDIM + sg*4); }       \
        _Pragma("unroll")                                                      \
        for (int q = 0; q < 4; q++) { int o = t + q*256, r = o >> 3, sg = o & 7; \
            cp16(bB[P] + r*ROWB + sg*16, Bs_ + (size_t)r*CDIM + sg*4); }       \
        cp_commit(); }

    PG_FILLG(0, 0)
    PG_FILLG(1, 1)

    for (int gc = 0; gc < 8; gc++) {
        if (gc + 1 < 8) cp_wait1(); else cp_wait0();
        __syncthreads();
        int p = gc & 1;
#pragma unroll
        for (int ks = 0; ks < 32; ks += 8) {
            float2 aF[4][2];
#pragma unroll
            for (int mt = 0; mt < 4; mt++) {
                int r0 = mrow + mt*16 + g;
                aF[mt][0] = *(float2*)&(*SA)[p][r0    ][ks + 2*tig];
                aF[mt][1] = *(float2*)&(*SA)[p][r0 + 8][ks + 2*tig];
            }
#pragma unroll
            for (int nt = 0; nt < 4; nt++) {
                float2 bF = *(float2*)&(*SB)[p][ncol + nt*8 + g][ks + 2*tig];
#pragma unroll
                for (int mt = 0; mt < 4; mt++)
                    mma8(acc[mt][nt],
                         __float_as_uint(aF[mt][0].x), __float_as_uint(aF[mt][1].x),
                         __float_as_uint(aF[mt][0].y), __float_as_uint(aF[mt][1].y),
                         __float_as_uint(bF.x), __float_as_uint(bF.y));
            }
        }
        __syncthreads();
        if (gc + 2 < 8) PG_FILLG(gc + 2, p)
        if ((gc & 3) == 3) {
            /* row-tile finished: epilogue overlaps in-flight fills */
            pg_epilogue(acc, rowbase0 + (gc >> 2) * 128, jbase, is_gl,
                        mrow, ncol, g, tig);
#pragma unroll
            for (int mt = 0; mt < 4; mt++)
#pragma unroll
                for (int nt = 0; nt < 4; nt++) {
                    acc[mt][nt][0] = 0.f; acc[mt][nt][1] = 0.f;
                    acc[mt][nt][2] = 0.f; acc[mt][nt][3] = 0.f;
                }
        }
    }
}

/* ------------------------------------------------------------------ */
/* K3: per-channel NT GEMM. block 128 x 128, warp 64x32. 2 CTAs/SM.    */
/* ------------------------------------------------------------------ */
__global__ __launch_bounds__(256, 2) void k_tri_m()
{
    extern __shared__ float dsm[];
    float (*SA)[2][128][SMPAD] = (float(*)[2][128][SMPAD])dsm;
    float (*SB)[2][128][SMPAD] = (float(*)[2][128][SMPAD])(dsm + 2*128*SMPAD);
    uint32_t sb = smem_u32(dsm);
    uint32_t bA[2] = { sb, sb + TILE128 };
    uint32_t bB[2] = { sb + 2*TILE128, sb + 3*TILE128 };

    int c = blockIdx.z;
    int ib = blockIdx.y * 128, jb = blockIdx.x * 128;
    int t = threadIdx.x, warp = t >> 5, lane = t & 31;
    int g = lane >> 2, tig = lane & 3;
    int mrow = (warp >> 2) * 64, ncol = (warp & 3) * 32;

    const float* Asrc = g_a + (size_t)c*NR + (size_t)ib*NSEQ;
    const float* Bsrc = g_b + (size_t)c*NR + (size_t)jb*NSEQ;

    float acc[4][4][4] = {};

#define TRI_FILL(CH, P)                                                        \
    {   _Pragma("unroll")                                                      \
        for (int q = 0; q < 4; q++) { int o = t + q*256, r = o >> 3, sg = o & 7; \
            cp16(bA[P] + r*ROWB + sg*16, Asrc + (size_t)r*NSEQ + (CH)*32 + sg*4); } \
        _Pragma("unroll")                                                      \
        for (int q = 0; q < 4; q++) { int o = t + q*256, r = o >> 3, sg = o & 7; \
            cp16(bB[P] + r*ROWB + sg*16, Bsrc + (size_t)r*NSEQ + (CH)*32 + sg*4); } \
        cp_commit(); }

    TRI_FILL(0, 0)
    TRI_FILL(1, 1)

    for (int ch = 0; ch < 24; ch++) {
        if (ch + 1 < 24) cp_wait1(); else cp_wait0();
        __syncthreads();
        int p = ch & 1;
#pragma unroll
        for (int ks = 0; ks < 32; ks += 8) {
            float2 aF[4][2];
#pragma unroll
            for (int mt = 0; mt < 4; mt++) {
                int r0 = mrow + mt*16 + g;
                aF[mt][0] = *(float2*)&(*SA)[p][r0    ][ks + 2*tig];
                aF[mt][1] = *(float2*)&(*SA)[p][r0 + 8][ks + 2*tig];
            }
#pragma unroll
            for (int nt = 0; nt < 4; nt++) {
                float2 bF = *(float2*)&(*SB)[p][ncol + nt*8 + g][ks + 2*tig];
#pragma unroll
                for (int mt = 0; mt < 4; mt++)
                    mma8(acc[mt][nt],
                         __float_as_uint(aF[mt][0].x), __float_as_uint(aF[mt][1].x),
                         __float_as_uint(aF[mt][0].y), __float_as_uint(aF[mt][1].y),
                         __float_as_uint(bF.x), __float_as_uint(bF.y));
            }
        }
        __syncthreads();
        if (ch + 2 < 24) TRI_FILL(ch + 2, p)
    }

    float* Cb = g_tri + (size_t)c * NR;
#pragma unroll
    for (int mt = 0; mt < 4; mt++)
#pragma unroll
        for (int nt = 0; nt < 4; nt++) {
            int r = ib + mrow + mt*16 + g;
            int col = jb + ncol + nt*8 + tig*2;
            *(float2*)(Cb + (size_t)r*NSEQ + col) =
                make_float2(acc[mt][nt][0], acc[mt][nt][1]);
            *(float2*)(Cb + (size_t)(r+8)*NSEQ + col) =
                make_float2(acc[mt][nt][2], acc[mt][nt][3]);
        }
}

/* ------------------------------------------------------------------ */
/* K4 (mma): tri tile -> LN over c -> mma with g_wout -> x glin -> out */
/* Single-buffer Bs (weights L2-resident) -> 96256 B -> 2 CTAs/SM.     */
/* ------------------------------------------------------------------ */
#define KF_T_OFF  0
#define KF_AS_OFF 8704
#define KF_BS_OFF 18944
#define KF_FLOATS (KF_BS_OFF + 128*SMPAD)   /* 24064 floats = 96256 B */
__global__ __launch_bounds__(256, 2) void k_final_m(
    const float* __restrict__ lncw, const float* __restrict__ lncb,
    float* __restrict__ out)
{
    extern __shared__ float dsm[];
    float* T  = dsm + KF_T_OFF;                 /* [c][j], stride 68 */
    float* As = dsm + KF_AS_OFF;                /* [ck][j][40]        */
    float* Bs = dsm + KF_BS_OFF;                /* [c'][40] single    */
    uint32_t sbB = smem_u32(dsm) + KF_BS_OFF * 4;

    __shared__ float red[2][4][64];
    __shared__ float muS[64], rsS[64];
    __shared__ float lw[CDIM], lb[CDIM];

    int t = threadIdx.x, warp = t >> 5, lane = t & 31;
    int g = lane >> 2, tig = lane & 3;
    int i = blockIdx.y;
    int jb = blockIdx.x * 64;
    int mrow = (warp >> 2) * 32, ncol = (warp & 3) * 32;

    if (t < CDIM) { lw[t] = lncw[t]; lb[t] = lncb[t]; }

#define KF_BFILL(CK)                                                           \
    {   _Pragma("unroll")                                                      \
        for (int q = 0; q < 4; q++) { int o = t + q*256, r = o >> 3, sg = o & 7; \
            cp16(sbB + r*ROWB + sg*16,                                          \
                 g_wout + (size_t)r*CDIM + (CK)*32 + sg*4); }                   \
        cp_commit(); }

    KF_BFILL(0)

#pragma unroll
    for (int it = 0; it < 8; it++) {
        int idx4 = it*256 + t;
        int cc = idx4 >> 4, jq = idx4 & 15;
        float4 v = *(const float4*)(g_tri + (size_t)cc*NR + i*NSEQ + jb + jq*4);
        T[cc*68 + jq*4 + 0] = v.x; T[cc*68 + jq*4 + 1] = v.y;
        T[cc*68 + jq*4 + 2] = v.z; T[cc*68 + jq*4 + 3] = v.w;
    }
    __syncthreads();

    {
        int jl = t & 63, part = t >> 6;
        float s = 0.f, s2 = 0.f;
        for (int cc = part*32; cc < part*32 + 32; cc++) {
            float v = T[cc*68 + jl]; s += v; s2 += v*v;
        }
        red[0][part][jl] = s; red[1][part][jl] = s2;
    }
    __syncthreads();
    if (t < 64) {
        float ss = red[0][0][t] + red[0][1][t] + red[0][2][t] + red[0][3][t];
        float q  = red[1][0][t] + red[1][1][t] + red[1][2][t] + red[1][3][t];
        float m   = ss * (1.f/CDIM);
        float var = q  * (1.f/CDIM) - m*m;
        muS[t] = m; rsS[t] = rsqrtf(var + LNEPS);
    }
    __syncthreads();

    {
        int cc = t & 31, half = t >> 5;
        int ck = half & 3, jh = half >> 2;
        int c  = ck*32 + cc;
        int pos = 2*(cc & 3) + ((cc & 4) >> 2) + (cc & ~7);
        float w = lw[c], bias = lb[c];
        const float* Trow = T + c*68;
        float* Abase = As + (ck*64 + jh*32) * SMPAD + pos;
#pragma unroll 8
        for (int jj = 0; jj < 32; jj++) {
            int j = jh*32 + jj;
            Abase[jj * SMPAD] = tf32f((Trow[j] - muS[j]) * rsS[j] * w + bias);
        }
    }

    float acc[2][4][4] = {};
    for (int ch = 0; ch < 4; ch++) {
        cp_wait0();
        __syncthreads();
        const float* Ac = As + ch*64*SMPAD;
#pragma unroll
        for (int ks = 0; ks < 32; ks += 8) {
            float2 aF[2][2];
#pragma unroll
            for (int mt = 0; mt < 2; mt++) {
                int r0 = mrow + mt*16 + g;
                aF[mt][0] = *(float2*)&Ac[(r0    )*SMPAD + ks + 2*tig];
                aF[mt][1] = *(float2*)&Ac[(r0 + 8)*SMPAD + ks + 2*tig];
            }
#pragma unroll
            for (int nt = 0; nt < 4; nt++) {
                float2 bF = *(float2*)&Bs[(ncol + nt*8 + g)*SMPAD + ks + 2*tig];
#pragma unroll
                for (int mt = 0; mt < 2; mt++)
                    mma8(acc[mt][nt],
                         __float_as_uint(aF[mt][0].x), __float_as_uint(aF[mt][1].x),
                         __float_as_uint(aF[mt][0].y), __float_as_uint(aF[mt][1].y),
                         __float_as_uint(bF.x), __float_as_uint(bF.y));
            }
        }
        __syncthreads();
        if (ch + 1 < 4) KF_BFILL(ch + 1)
    }

#pragma unroll
    for (int mt = 0; mt < 2; mt++)
#pragma unroll
        for (int nt = 0; nt < 4; nt++) {
            int j   = mrow + mt*16 + g;
            int col = ncol + nt*8 + tig*2;
            size_t r0 = ((size_t)(i*NSEQ + jb + j)) * CDIM + col;
            size_t r1 = ((size_t)(i*NSEQ + jb + j + 8)) * CDIM + col;
            float2 gl0 = *(const float2*)(g_glin + r0);
            float2 gl1 = *(const float2*)(g_glin + r1);
            *(float2*)(out + r0) = make_float2(acc[mt][nt][0]*gl0.x,
                                               acc[mt][nt][1]*gl0.y);
            *(float2*)(out + r1) = make_float2(acc[mt][nt][2]*gl1.x,
                                               acc[mt][nt][3]*gl1.y);
        }
}

/* ------------------------------------------------------------------ */
extern "C" void kernel_launch(void* const* d_in, const int* in_sizes, int n_in,
                              void* d_out, int out_size)
{
    const float* pair    = (const float*)d_in[0];
    const float* ln_in_w = (const float*)d_in[1];
    const float* ln_in_b = (const float*)d_in[2];
    const float* w_proj  = (const float*)d_in[3];
    const float* w_gate  = (const float*)d_in[4];
    const float* ln_c_w  = (const float*)d_in[5];
    const float* ln_c_b  = (const float*)d_in[6];
    const float* w_out   = (const float*)d_in[7];
    const float* w_glin  = (const float*)d_in[8];
    float* out = (float*)d_out;

    const int GL_SMEM  = 4*TILE128;          /* 81920 (pg, tri) */
    const int KF_SMEM  = KF_FLOATS * 4;      /* 96256 -> 2 CTAs */
    static int attr_done = 0;
    if (!attr_done) {
        cudaFuncSetAttribute(k_pg_m,    cudaFuncAttributeMaxDynamicSharedMemorySize, GL_SMEM);
        cudaFuncSetAttribute(k_tri_m,   cudaFuncAttributeMaxDynamicSharedMemorySize, GL_SMEM);
        cudaFuncSetAttribute(k_final_m, cudaFuncAttributeMaxDynamicSharedMemorySize, KF_SMEM);
        cudaFuncSetAttribute(k_pg_m,    cudaFuncAttributePreferredSharedMemoryCarveout, 100);
        cudaFuncSetAttribute(k_tri_m,   cudaFuncAttributePreferredSharedMemoryCarveout, 100);
        cudaFuncSetAttribute(k_final_m, cudaFuncAttributePreferredSharedMemoryCarveout, 100);
        attr_done = 1;
    }

    k_ln     <<<NR/8, 256>>>(pair, ln_in_w, ln_in_b);
    k_round_w<<<96, 256>>>(w_proj, w_gate, w_glin, w_out);
    k_pg_m   <<<dim3(5, NR/256), 256, GL_SMEM>>>();
    k_tri_m  <<<dim3(6, 6, 128), 256, GL_SMEM>>>();
    k_final_m<<<dim3(12, NSEQ), 256, KF_SMEM>>>(ln_c_w, ln_c_b, out);
}

// round 17
// speedup vs baseline: 1.0104x; 1.0104x over previous
#include <cuda_runtime.h>
#include <cstdint>

#define NSEQ 768
#define CDIM 128
#define NR (NSEQ*NSEQ)          /* 589824 */
#define LNEPS 1e-5f

static constexpr size_t BUF_ELEMS = (size_t)CDIM * NR;

/* K-pair permuted layouts: within each 8-group of the contraction dim,
   element k sits at offset (k&~7) + 2*(k&3) + ((k&4)>>2). */
__device__ float g_x[BUF_ELEMS];       /* LN'd, tf32, permuted [row][perm(c)] */
__device__ float g_wpg[512*CDIM];      /* interleaved proj/gate rows (512), tf32, permuted */
__device__ float g_wgl[CDIM*CDIM];     /* w_glin, tf32, permuted */
__device__ float g_wout[CDIM*CDIM];    /* w_out, tf32, permuted */
__device__ float g_a[BUF_ELEMS];       /* [c][i][perm(k)] tf32 */
__device__ float g_b[BUF_ELEMS];       /* [c][j][perm(k)] tf32 */
__device__ float g_glin[BUF_ELEMS];    /* [row][c] sigmoid, fp32, plain */
__device__ float g_tri[BUF_ELEMS];     /* [c][i][j] plain */

/* ---------------- helpers ------------------------------------------ */
__device__ __forceinline__ uint32_t smem_u32(const void* p) {
    uint32_t a;
    asm("{ .reg .u64 t; cvta.to.shared.u64 t, %1; cvt.u32.u64 %0, t; }"
        : "=r"(a) : "l"(p));
    return a;
}
__device__ __forceinline__ uint32_t tf32u(float x) {
    uint32_t r;
    asm("cvt.rna.tf32.f32 %0, %1;" : "=r"(r) : "f"(x));
    return r;
}
__device__ __forceinline__ float tf32f(float x) { return __uint_as_float(tf32u(x)); }
__device__ __forceinline__ float sigm(float x)  { return 1.f / (1.f + __expf(-x)); }
__device__ __forceinline__ int   perm8(int k)   { return (k & ~7) + 2*(k&3) + ((k&4)>>2); }

__device__ __forceinline__ void mma8(float* c, uint32_t a0, uint32_t a1,
                                     uint32_t a2, uint32_t a3,
                                     uint32_t b0, uint32_t b1) {
    asm volatile(
        "mma.sync.aligned.m16n8k8.row.col.f32.tf32.tf32.f32 "
        "{%0,%1,%2,%3}, {%4,%5,%6,%7}, {%8,%9}, {%0,%1,%2,%3};"
        : "+f"(c[0]), "+f"(c[1]), "+f"(c[2]), "+f"(c[3])
        : "r"(a0), "r"(a1), "r"(a2), "r"(a3), "r"(b0), "r"(b1));
}
__device__ __forceinline__ void cp16(uint32_t d, const void* s) {
    asm volatile("cp.async.cg.shared.global [%0], [%1], 16;" :: "r"(d), "l"(s));
}
__device__ __forceinline__ void cp_commit() { asm volatile("cp.async.commit_group;"); }
__device__ __forceinline__ void cp_wait1()  { asm volatile("cp.async.wait_group 1;"); }
__device__ __forceinline__ void cp_wait0()  { asm volatile("cp.async.wait_group 0;"); }

/* smem rows: 32 data floats padded to 40 (160B, 16B-aligned) */
#define SMPAD 40
#define ROWB  160
#define TILE128 20480          /* 128*160 */

/* ------------------------------------------------------------------ */
/* K0 (merged): LN+permute for pair rows, plus weight rounding in tail */
/* blocks. grid = NR/8 + 96.                                           */
/* ------------------------------------------------------------------ */
__global__ void k_ln(const float* __restrict__ pair,
                     const float* __restrict__ lnw, const float* __restrict__ lnb,
                     const float* __restrict__ wp, const float* __restrict__ wg,
                     const float* __restrict__ wgl, const float* __restrict__ wout)
{
    if (blockIdx.x < NR/8) {
        int row  = blockIdx.x * 8 + (threadIdx.x >> 5);
        int lane = threadIdx.x & 31;
        float4 v = ((const float4*)(pair + (size_t)row * CDIM))[lane];
        float s  = v.x + v.y + v.z + v.w;
        float s2 = v.x*v.x + v.y*v.y + v.z*v.z + v.w*v.w;
#pragma unroll
        for (int o = 16; o > 0; o >>= 1) {
            s  += __shfl_xor_sync(0xffffffffu, s,  o);
            s2 += __shfl_xor_sync(0xffffffffu, s2, o);
        }
        float m  = s * (1.f/CDIM);
        float rs = rsqrtf(s2 * (1.f/CDIM) - m*m + LNEPS);
        int c0 = lane * 4;
        float* dst = g_x + (size_t)row * CDIM;
        float o0 = tf32f((v.x - m) * rs * __ldg(lnw+c0+0) + __ldg(lnb+c0+0));
        float o1 = tf32f((v.y - m) * rs * __ldg(lnw+c0+1) + __ldg(lnb+c0+1));
        float o2 = tf32f((v.z - m) * rs * __ldg(lnw+c0+2) + __ldg(lnb+c0+2));
        float o3 = tf32f((v.w - m) * rs * __ldg(lnw+c0+3) + __ldg(lnb+c0+3));
        dst[perm8(c0+0)] = o0; dst[perm8(c0+1)] = o1;
        dst[perm8(c0+2)] = o2; dst[perm8(c0+3)] = o3;
    } else {
        int i4 = (blockIdx.x - NR/8) * 256 + threadIdx.x;
        if (i4 < 16384) {
            int q = i4 >> 5, kq = (i4 & 31) * 4;
            const float* src = ((q & 1) ? wg : wp) + (size_t)(q >> 1) * CDIM + kq;
            float* dst = g_wpg + (size_t)q * CDIM;
            float4 v = *(const float4*)src;
            dst[perm8(kq+0)] = tf32f(v.x); dst[perm8(kq+1)] = tf32f(v.y);
            dst[perm8(kq+2)] = tf32f(v.z); dst[perm8(kq+3)] = tf32f(v.w);
        } else if (i4 < 20480) {
            int j = i4 - 16384, q = j >> 5, kq = (j & 31) * 4;
            float4 v = *(const float4*)(wgl + (size_t)q * CDIM + kq);
            float* dst = g_wgl + (size_t)q * CDIM;
            dst[perm8(kq+0)] = tf32f(v.x); dst[perm8(kq+1)] = tf32f(v.y);
            dst[perm8(kq+2)] = tf32f(v.z); dst[perm8(kq+3)] = tf32f(v.w);
        } else if (i4 < 24576) {
            int j = i4 - 20480, q = j >> 5, kq = (j & 31) * 4;
            float4 v = *(const float4*)(wout + (size_t)q * CDIM + kq);
            float* dst = g_wout + (size_t)q * CDIM;
            dst[perm8(kq+0)] = tf32f(v.x); dst[perm8(kq+1)] = tf32f(v.y);
            dst[perm8(kq+2)] = tf32f(v.z); dst[perm8(kq+3)] = tf32f(v.w);
        }
    }
}

/* ------------------------------------------------------------------ */
/* K2 (merged pg+glin): block 128 rows x 128 mma cols, warp 64x32.     */
/* grid (5, NR/128): x<4 -> proj/gate cols; x==4 -> glin.              */
/* ------------------------------------------------------------------ */
__global__ __launch_bounds__(256, 2) void k_pg_m()
{
    extern __shared__ float dsm[];
    float (*SA)[2][128][SMPAD] = (float(*)[2][128][SMPAD])dsm;
    float (*SB)[2][128][SMPAD] = (float(*)[2][128][SMPAD])(dsm + 2*128*SMPAD);
    uint32_t sb = smem_u32(dsm);
    uint32_t bA[2] = { sb, sb + TILE128 };
    uint32_t bB[2] = { sb + 2*TILE128, sb + 3*TILE128 };

    int t = threadIdx.x, warp = t >> 5, lane = t & 31;
    int g = lane >> 2, tig = lane & 3;
    int bx = blockIdx.x;
    int rowbase = blockIdx.y * 128;
    int is_gl = (bx == 4);
    int jbase  = bx * 64;
    int mrow = (warp >> 2) * 64, ncol = (warp & 3) * 32;

    const float* Asrc = g_x + (size_t)rowbase * CDIM;
    const float* Bsrc = is_gl ? g_wgl : (g_wpg + (size_t)(jbase * 2) * CDIM);

    float acc[4][4][4] = {};

#define PG_FILL(CH, P)                                                         \
    {   _Pragma("unroll")                                                      \
        for (int q = 0; q < 4; q++) { int o = t + q*256, r = o >> 3, sg = o & 7; \
            cp16(bA[P] + r*ROWB + sg*16, Asrc + (size_t)r*CDIM + (CH)*32 + sg*4); } \
        _Pragma("unroll")                                                      \
        for (int q = 0; q < 4; q++) { int o = t + q*256, r = o >> 3, sg = o & 7; \
            cp16(bB[P] + r*ROWB + sg*16, Bsrc + (size_t)r*CDIM + (CH)*32 + sg*4); } \
        cp_commit(); }

    PG_FILL(0, 0)
    PG_FILL(1, 1)

    for (int ch = 0; ch < 4; ch++) {
        if (ch + 1 < 4) cp_wait1(); else cp_wait0();
        __syncthreads();
        int p = ch & 1;
#pragma unroll
        for (int ks = 0; ks < 32; ks += 8) {
            float2 aF[4][2];
#pragma unroll
            for (int mt = 0; mt < 4; mt++) {
                int r0 = mrow + mt*16 + g;
                aF[mt][0] = *(float2*)&(*SA)[p][r0    ][ks + 2*tig];
                aF[mt][1] = *(float2*)&(*SA)[p][r0 + 8][ks + 2*tig];
            }
#pragma unroll
            for (int nt = 0; nt < 4; nt++) {
                float2 bF = *(float2*)&(*SB)[p][ncol + nt*8 + g][ks + 2*tig];
#pragma unroll
                for (int mt = 0; mt < 4; mt++)
                    mma8(acc[mt][nt],
                         __float_as_uint(aF[mt][0].x), __float_as_uint(aF[mt][1].x),
                         __float_as_uint(aF[mt][0].y), __float_as_uint(aF[mt][1].y),
                         __float_as_uint(bF.x), __float_as_uint(bF.y));
            }
        }
        __syncthreads();
        if (ch + 2 < 4) PG_FILL(ch + 2, p)
    }

    if (!is_gl) {
        int pg_off = 2*(g & 3) + ((g & 4) >> 2);
#pragma unroll
        for (int mt = 0; mt < 4; mt++)
#pragma unroll
            for (int nt = 0; nt < 4; nt++) {
                int rg = rowbase + mrow + mt*16 + g;
                int n0 = ncol + nt*8 + tig*2;
                int jo = jbase + (n0 >> 1);
                float* dst = (jo & 1) ? g_b : g_a;
                size_t base = (size_t)(jo >> 1) * NR + (rg - g) + pg_off;
                dst[base]     = tf32f(acc[mt][nt][0] * sigm(acc[mt][nt][1]));
                dst[base + 8] = tf32f(acc[mt][nt][2] * sigm(acc[mt][nt][3]));
            }
    } else {
#pragma unroll
        for (int mt = 0; mt < 4; mt++)
#pragma unroll
            for (int nt = 0; nt < 4; nt++) {
                int rg = rowbase + mrow + mt*16 + g;
                int col = ncol + nt*8 + tig*2;
                *(float2*)(g_glin + (size_t)rg * CDIM + col) =
                    make_float2(sigm(acc[mt][nt][0]), sigm(acc[mt][nt][1]));
                *(float2*)(g_glin + (size_t)(rg+8) * CDIM + col) =
                    make_float2(sigm(acc[mt][nt][2]), sigm(acc[mt][nt][3]));
            }
    }
}

/* ------------------------------------------------------------------ */
/* K3: per-channel NT GEMM. block 128 x 128, warp 64x32. 2 CTAs/SM.    */
/* ------------------------------------------------------------------ */
__global__ __launch_bounds__(256, 2) void k_tri_m()
{
    extern __shared__ float dsm[];
    float (*SA)[2][128][SMPAD] = (float(*)[2][128][SMPAD])dsm;
    float (*SB)[2][128][SMPAD] = (float(*)[2][128][SMPAD])(dsm + 2*128*SMPAD);
    uint32_t sb = smem_u32(dsm);
    uint32_t bA[2] = { sb, sb + TILE128 };
    uint32_t bB[2] = { sb + 2*TILE128, sb + 3*TILE128 };

    int c = blockIdx.z;
    int ib = blockIdx.y * 128, jb = blockIdx.x * 128;
    int t = threadIdx.x, warp = t >> 5, lane = t & 31;
    int g = lane >> 2, tig = lane & 3;
    int mrow = (warp >> 2) * 64, ncol = (warp & 3) * 32;

    const float* Asrc = g_a + (size_t)c*NR + (size_t)ib*NSEQ;
    const float* Bsrc = g_b + (size_t)c*NR + (size_t)jb*NSEQ;

    float acc[4][4][4] = {};

#define TRI_FILL(CH, P)                                                        \
    {   _Pragma("unroll")                                                      \
        for (int q = 0; q < 4; q++) { int o = t + q*256, r = o >> 3, sg = o & 7; \
            cp16(bA[P] + r*ROWB + sg*16, Asrc + (size_t)r*NSEQ + (CH)*32 + sg*4); } \
        _Pragma("unroll")                                                      \
        for (int q = 0; q < 4; q++) { int o = t + q*256, r = o >> 3, sg = o & 7; \
            cp16(bB[P] + r*ROWB + sg*16, Bsrc + (size_t)r*NSEQ + (CH)*32 + sg*4); } \
        cp_commit(); }

    TRI_FILL(0, 0)
    TRI_FILL(1, 1)

    for (int ch = 0; ch < 24; ch++) {
        if (ch + 1 < 24) cp_wait1(); else cp_wait0();
        __syncthreads();
        int p = ch & 1;
#pragma unroll
        for (int ks = 0; ks < 32; ks += 8) {
            float2 aF[4][2];
#pragma unroll
            for (int mt = 0; mt < 4; mt++) {
                int r0 = mrow + mt*16 + g;
                aF[mt][0] = *(float2*)&(*SA)[p][r0    ][ks + 2*tig];
                aF[mt][1] = *(float2*)&(*SA)[p][r0 + 8][ks + 2*tig];
            }
#pragma unroll
            for (int nt = 0; nt < 4; nt++) {
                float2 bF = *(float2*)&(*SB)[p][ncol + nt*8 + g][ks + 2*tig];
#pragma unroll
                for (int mt = 0; mt < 4; mt++)
                    mma8(acc[mt][nt],
                         __float_as_uint(aF[mt][0].x), __float_as_uint(aF[mt][1].x),
                         __float_as_uint(aF[mt][0].y), __float_as_uint(aF[mt][1].y),
                         __float_as_uint(bF.x), __float_as_uint(bF.y));
            }
        }
        __syncthreads();
        if (ch + 2 < 24) TRI_FILL(ch + 2, p)
    }

    float* Cb = g_tri + (size_t)c * NR;
#pragma unroll
    for (int mt = 0; mt < 4; mt++)
#pragma unroll
        for (int nt = 0; nt < 4; nt++) {
            int r = ib + mrow + mt*16 + g;
            int col = jb + ncol + nt*8 + tig*2;
            *(float2*)(Cb + (size_t)r*NSEQ + col) =
                make_float2(acc[mt][nt][0], acc[mt][nt][1]);
            *(float2*)(Cb + (size_t)(r+8)*NSEQ + col) =
                make_float2(acc[mt][nt][2], acc[mt][nt][3]);
        }
}

/* ------------------------------------------------------------------ */
/* K4 (mma): tri tile -> LN over c -> mma with g_wout -> x glin -> out */
/* Single-buffer Bs (weights L2-resident) -> 96256 B -> 2 CTAs/SM.     */
/* ------------------------------------------------------------------ */
#define KF_T_OFF  0
#define KF_AS_OFF 8704
#define KF_BS_OFF 18944
#define KF_FLOATS (KF_BS_OFF + 128*SMPAD)   /* 24064 floats = 96256 B */
__global__ __launch_bounds__(256, 2) void k_final_m(
    const float* __restrict__ lncw, const float* __restrict__ lncb,
    float* __restrict__ out)
{
    extern __shared__ float dsm[];
    float* T  = dsm + KF_T_OFF;                 /* [c][j], stride 68 */
    float* As = dsm + KF_AS_OFF;                /* [ck][j][40]        */
    float* Bs = dsm + KF_BS_OFF;                /* [c'][40] single    */
    uint32_t sbB = smem_u32(dsm) + KF_BS_OFF * 4;

    __shared__ float red[2][4][64];
    __shared__ float muS[64], rsS[64];
    __shared__ float lw[CDIM], lb[CDIM];

    int t = threadIdx.x, warp = t >> 5, lane = t & 31;
    int g = lane >> 2, tig = lane & 3;
    int i = blockIdx.y;
    int jb = blockIdx.x * 64;
    int mrow = (warp >> 2) * 32, ncol = (warp & 3) * 32;

    if (t < CDIM) { lw[t] = lncw[t]; lb[t] = lncb[t]; }

#define KF_BFILL(CK)                                                           \
    {   _Pragma("unroll")                                                      \
        for (int q = 0; q < 4; q++) { int o = t + q*256, r = o >> 3, sg = o & 7; \
            cp16(sbB + r*ROWB + sg*16,                                          \
                 g_wout + (size_t)r*CDIM + (CK)*32 + sg*4); }                   \
        cp_commit(); }

    KF_BFILL(0)

#pragma unroll
    for (int it = 0; it < 8; it++) {
        int idx4 = it*256 + t;
        int cc = idx4 >> 4, jq = idx4 & 15;
        float4 v = *(const float4*)(g_tri + (size_t)cc*NR + i*NSEQ + jb + jq*4);
        T[cc*68 + jq*4 + 0] = v.x; T[cc*68 + jq*4 + 1] = v.y;
        T[cc*68 + jq*4 + 2] = v.z; T[cc*68 + jq*4 + 3] = v.w;
    }
    __syncthreads();

    {
        int jl = t & 63, part = t >> 6;
        float s = 0.f, s2 = 0.f;
        for (int cc = part*32; cc < part*32 + 32; cc++) {
            float v = T[cc*68 + jl]; s += v; s2 += v*v;
        }
        red[0][part][jl] = s; red[1][part][jl] = s2;
    }
    __syncthreads();
    if (t < 64) {
        float ss = red[0][0][t] + red[0][1][t] + red[0][2][t] + red[0][3][t];
        float q  = red[1][0][t] + red[1][1][t] + red[1][2][t] + red[1][3][t];
        float m   = ss * (1.f/CDIM);
        float var = q  * (1.f/CDIM) - m*m;
        muS[t] = m; rsS[t] = rsqrtf(var + LNEPS);
    }
    __syncthreads();

    {
        int cc = t & 31, half = t >> 5;
        int ck = half & 3, jh = half >> 2;
        int c  = ck*32 + cc;
        int pos = 2*(cc & 3) + ((cc & 4) >> 2) + (cc & ~7);
        float w = lw[c], bias = lb[c];
        const float* Trow = T + c*68;
        float* Abase = As + (ck*64 + jh*32) * SMPAD + pos;
#pragma unroll 8
        for (int jj = 0; jj < 32; jj++) {
            int j = jh*32 + jj;
            Abase[jj * SMPAD] = tf32f((Trow[j] - muS[j]) * rsS[j] * w + bias);
        }
    }

    float acc[2][4][4] = {};
    for (int ch = 0; ch < 4; ch++) {
        cp_wait0();
        __syncthreads();
        const float* Ac = As + ch*64*SMPAD;
#pragma unroll
        for (int ks = 0; ks < 32; ks += 8) {
            float2 aF[2][2];
#pragma unroll
            for (int mt = 0; mt < 2; mt++) {
                int r0 = mrow + mt*16 + g;
                aF[mt][0] = *(float2*)&Ac[(r0    )*SMPAD + ks + 2*tig];
                aF[mt][1] = *(float2*)&Ac[(r0 + 8)*SMPAD + ks + 2*tig];
            }
#pragma unroll
            for (int nt = 0; nt < 4; nt++) {
                float2 bF = *(float2*)&Bs[(ncol + nt*8 + g)*SMPAD + ks + 2*tig];
#pragma unroll
                for (int mt = 0; mt < 2; mt++)
                    mma8(acc[mt][nt],
                         __float_as_uint(aF[mt][0].x), __float_as_uint(aF[mt][1].x),
                         __float_as_uint(aF[mt][0].y), __float_as_uint(aF[mt][1].y),
                         __float_as_uint(bF.x), __float_as_uint(bF.y));
            }
        }
        __syncthreads();
        if (ch + 1 < 4) KF_BFILL(ch + 1)
    }

#pragma unroll
    for (int mt = 0; mt < 2; mt++)
#pragma unroll
        for (int nt = 0; nt < 4; nt++) {
            int j   = mrow + mt*16 + g;
            int col = ncol + nt*8 + tig*2;
            size_t r0 = ((size_t)(i*NSEQ + jb + j)) * CDIM + col;
            size_t r1 = ((size_t)(i*NSEQ + jb + j + 8)) * CDIM + col;
            float2 gl0 = *(const float2*)(g_glin + r0);
            float2 gl1 = *(const float2*)(g_glin + r1);
            *(float2*)(out + r0) = make_float2(acc[mt][nt][0]*gl0.x,
                                               acc[mt][nt][1]*gl0.y);
            *(float2*)(out + r1) = make_float2(acc[mt][nt][2]*gl1.x,
                                               acc[mt][nt][3]*gl1.y);
        }
}

/* ------------------------------------------------------------------ */
extern "C" void kernel_launch(void* const* d_in, const int* in_sizes, int n_in,
                              void* d_out, int out_size)
{
    const float* pair    = (const float*)d_in[0];
    const float* ln_in_w = (const float*)d_in[1];
    const float* ln_in_b = (const float*)d_in[2];
    const float* w_proj  = (const float*)d_in[3];
    const float* w_gate  = (const float*)d_in[4];
    const float* ln_c_w  = (const float*)d_in[5];
    const float* ln_c_b  = (const float*)d_in[6];
    const float* w_out   = (const float*)d_in[7];
    const float* w_glin  = (const float*)d_in[8];
    float* out = (float*)d_out;

    const int GL_SMEM  = 4*TILE128;          /* 81920 (pg, tri) */
    const int KF_SMEM  = KF_FLOATS * 4;      /* 96256 -> 2 CTAs */
    static int attr_done = 0;
    if (!attr_done) {
        cudaFuncSetAttribute(k_pg_m,    cudaFuncAttributeMaxDynamicSharedMemorySize, GL_SMEM);
        cudaFuncSetAttribute(k_tri_m,   cudaFuncAttributeMaxDynamicSharedMemorySize, GL_SMEM);
        cudaFuncSetAttribute(k_final_m, cudaFuncAttributeMaxDynamicSharedMemorySize, KF_SMEM);
        cudaFuncSetAttribute(k_pg_m,    cudaFuncAttributePreferredSharedMemoryCarveout, 100);
        cudaFuncSetAttribute(k_tri_m,   cudaFuncAttributePreferredSharedMemoryCarveout, 100);
        cudaFuncSetAttribute(k_final_m, cudaFuncAttributePreferredSharedMemoryCarveout, 100);
        attr_done = 1;
    }

    k_ln     <<<NR/8 + 96, 256>>>(pair, ln_in_w, ln_in_b,
                                  w_proj, w_gate, w_glin, w_out);
    k_pg_m   <<<dim3(5, NR/128), 256, GL_SMEM>>>();
    k_tri_m  <<<dim3(6, 6, 128), 256, GL_SMEM>>>();
    k_final_m<<<dim3(12, NSEQ), 256, KF_SMEM>>>(ln_c_w, ln_c_b, out);
}